// round 6
// baseline (speedup 1.0000x reference)
#include <cuda_runtime.h>
#include <cuda_bf16.h>
#include <math.h>

// Problem constants
#define N    2048
#define DH   256
#define DK   64
#define FF   32

typedef unsigned long long u64;

// ---------------------------------------------------------------------------
// f32x2 packed helpers (Blackwell sm_100+ only; ptxas never auto-fuses these)
// ---------------------------------------------------------------------------
__device__ __forceinline__ u64 pack2(float lo, float hi) {
    u64 r;
    asm("mov.b64 %0, {%1, %2};" : "=l"(r) : "f"(lo), "f"(hi));
    return r;
}
__device__ __forceinline__ void unpack2(u64 v, float& lo, float& hi) {
    asm("mov.b64 {%0, %1}, %2;" : "=f"(lo), "=f"(hi) : "l"(v));
}
__device__ __forceinline__ u64 fma2(u64 a, u64 b, u64 c) {
    u64 d;
    asm("fma.rn.f32x2 %0, %1, %2, %3;" : "=l"(d) : "l"(a), "l"(b), "l"(c));
    return d;
}
__device__ __forceinline__ u64 dup2(float v) { return pack2(v, v); }
__device__ __forceinline__ u64 relu2(u64 a) {
    float lo, hi;
    unpack2(a, lo, hi);
    lo = fmaxf(lo, 0.0f);
    hi = fmaxf(hi, 0.0f);
    return pack2(lo, hi);
}

// ---------------------------------------------------------------------------
// Scratch (no cudaMalloc allowed)
// ---------------------------------------------------------------------------
__device__ float g_q[N * DK];       // Q(x_j): (N, 64)
__device__ float g_k[N * DK];       // K(x_i): (N, 64)
__device__ float g_v[N * DH];       // V(x_j): (N, 256)
__device__ float g_scores[(size_t)N * N];  // k @ q^T
__device__ float g_p[(size_t)N * N];       // softmax focus

// ---------------------------------------------------------------------------
// Kernel A: q/k/v projections. 128 blocks x 16 rows. x tile cached in smem,
// weight-column loop outermost so W is read once per block (50 MB total L2).
// ---------------------------------------------------------------------------
#define A_ROWS 16
__global__ void __launch_bounds__(256) proj_kernel(
    const float* __restrict__ x,
    const float* __restrict__ Wq, const float* __restrict__ bq,
    const float* __restrict__ Wk, const float* __restrict__ bk,
    const float* __restrict__ Wv, const float* __restrict__ bv)
{
    __shared__ float xs[A_ROWS * DH];   // 16 KB
    const int tid = threadIdx.x;
    const int r0  = blockIdx.x * A_ROWS;

    for (int idx = tid; idx < A_ROWS * DH; idx += 256)
        xs[idx] = x[(size_t)r0 * DH + idx];
    __syncthreads();

    // 384 output columns total: [0,64) -> q, [64,128) -> k, [128,384) -> v
    for (int g = tid; g < 384; g += 256) {
        const float* W; const float* b; float* out;
        int ld, col;
        if (g < 64)        { W = Wq; b = bq; out = g_q; ld = DK; col = g; }
        else if (g < 128)  { W = Wk; b = bk; out = g_k; ld = DK; col = g - 64; }
        else               { W = Wv; b = bv; out = g_v; ld = DH; col = g - 128; }

        float acc[A_ROWS];
        const float bb = b[col];
#pragma unroll
        for (int r = 0; r < A_ROWS; r++) acc[r] = bb;

        for (int k = 0; k < DH; k++) {
            const float w = W[k * ld + col];
#pragma unroll
            for (int r = 0; r < A_ROWS; r++)
                acc[r] = fmaf(xs[r * DH + k], w, acc[r]);
        }
#pragma unroll
        for (int r = 0; r < A_ROWS; r++)
            out[(size_t)(r0 + r) * ld + col] = acc[r];
    }
}

// ---------------------------------------------------------------------------
// Kernel B: scores[i][j] = dot(k_i, q_j). 64x64 output tile per block,
// transposed smem tiles (conflict-free), 4x4 thread micro-tile, float4 store.
// ---------------------------------------------------------------------------
__global__ void __launch_bounds__(256) scores_kernel()
{
    __shared__ float ks[64 * 65];  // ks[c][i]
    __shared__ float qs[64 * 65];  // qs[c][j]
    const int tid = threadIdx.x;
    const int j0 = blockIdx.x * 64;
    const int i0 = blockIdx.y * 64;

    for (int idx = tid; idx < 64 * 64; idx += 256) {
        const int row = idx >> 6;   // tile row
        const int c   = idx & 63;   // k-dim
        ks[c * 65 + row] = g_k[(size_t)(i0 + row) * DK + c];
        qs[c * 65 + row] = g_q[(size_t)(j0 + row) * DK + c];
    }
    __syncthreads();

    const int ty = tid >> 4, tx = tid & 15;
    float acc[4][4];
#pragma unroll
    for (int r = 0; r < 4; r++)
#pragma unroll
        for (int c = 0; c < 4; c++) acc[r][c] = 0.0f;

#pragma unroll 8
    for (int c = 0; c < 64; c++) {
        float a[4], bv[4];
#pragma unroll
        for (int r = 0; r < 4; r++) a[r]  = ks[c * 65 + ty * 4 + r];
#pragma unroll
        for (int j = 0; j < 4; j++) bv[j] = qs[c * 65 + tx * 4 + j];
#pragma unroll
        for (int r = 0; r < 4; r++)
#pragma unroll
            for (int j = 0; j < 4; j++)
                acc[r][j] = fmaf(a[r], bv[j], acc[r][j]);
    }

#pragma unroll
    for (int r = 0; r < 4; r++) {
        float4 o = make_float4(acc[r][0], acc[r][1], acc[r][2], acc[r][3]);
        *reinterpret_cast<float4*>(
            &g_scores[(size_t)(i0 + ty * 4 + r) * N + j0 + tx * 4]) = o;
    }
}

// ---------------------------------------------------------------------------
// Kernel C: fused per-pair MLP + row softmax -> P.
// One block per row i. 256 threads x 4 chunks, each thread owns 4 f32x2
// j-pairs. W2 stored value-duplicated in smem so one broadcast LDS.64 feeds
// each fma.rn.f32x2 (issue slots: FFMA2 and LDS alternate at rt=2 -> free).
// b3 is softmax-invariant and dropped.
// ---------------------------------------------------------------------------
__global__ void __launch_bounds__(256, 2) mlp_softmax_kernel(
    const float* __restrict__ adj,  const float* __restrict__ dense,
    const float* __restrict__ W1,   const float* __restrict__ b1,
    const float* __restrict__ W2,   const float* __restrict__ b2,
    const float* __restrict__ W3)
{
    __shared__ u64 w2p[FF * FF];                       // 8 KB, duplicated pairs
    __shared__ u64 c0p[FF], c1p[FF], c2p[FF], b1p[FF], b2p[FF], w3p[FF];
    __shared__ float redbuf[8];

    const int tid = threadIdx.x;

    if (tid < FF) {
        c0p[tid] = dup2(W1[0 * FF + tid]);   // scores coeff
        c1p[tid] = dup2(W1[1 * FF + tid]);   // adj coeff
        c2p[tid] = dup2(W1[2 * FF + tid]);   // dense coeff
        b1p[tid] = dup2(b1[tid]);
        b2p[tid] = dup2(b2[tid]);
        w3p[tid] = dup2(W3[tid]);
    }
    for (int idx = tid; idx < FF * FF; idx += 256)
        w2p[idx] = dup2(W2[idx]);
    __syncthreads();

    const int i = blockIdx.x;
    const float2* srow = reinterpret_cast<const float2*>(g_scores + (size_t)i * N);
    const float2* arow = reinterpret_cast<const float2*>(adj      + (size_t)i * N);
    const float2* drow = reinterpret_cast<const float2*>(dense    + (size_t)i * N);

    float lv[8];
    float lmax = -1e30f;

    for (int p = 0; p < 4; p++) {
        const int jj = p * 256 + tid;     // float2 index: covers j = 2jj, 2jj+1
        const float2 s = srow[jj];
        const float2 a = arow[jj];
        const float2 d = drow[jj];
        const u64 s2 = pack2(s.x, s.y);
        const u64 a2 = pack2(a.x, a.y);
        const u64 d2 = pack2(d.x, d.y);

        // h1 = relu(s*W1[0] + a*W1[1] + d*W1[2] + b1)
        u64 h1[FF];
#pragma unroll
        for (int ii = 0; ii < FF; ii++) {
            u64 t = fma2(d2, c2p[ii], b1p[ii]);
            t = fma2(a2, c1p[ii], t);
            t = fma2(s2, c0p[ii], t);
            h1[ii] = relu2(t);
        }

        // logit = sum_o relu(b2[o] + sum_i h1[i]*W2[i][o]) * W3[o]
        u64 lg = 0ULL;  // (0.0f, 0.0f)
#pragma unroll 2
        for (int o = 0; o < FF; o++) {
            u64 acc = b2p[o];
#pragma unroll
            for (int ii = 0; ii < FF; ii++)
                acc = fma2(h1[ii], w2p[ii * FF + o], acc);
            acc = relu2(acc);
            lg = fma2(acc, w3p[o], lg);
        }
        float lo, hi;
        unpack2(lg, lo, hi);
        lv[2 * p]     = lo;
        lv[2 * p + 1] = hi;
        lmax = fmaxf(lmax, fmaxf(lo, hi));
    }

    // ---- block-reduce max ----
#pragma unroll
    for (int off = 16; off > 0; off >>= 1)
        lmax = fmaxf(lmax, __shfl_xor_sync(0xffffffffu, lmax, off));
    if ((tid & 31) == 0) redbuf[tid >> 5] = lmax;
    __syncthreads();
    float m;
    {
        float v = redbuf[tid & 7];
#pragma unroll
        for (int off = 4; off > 0; off >>= 1)
            v = fmaxf(v, __shfl_xor_sync(0xffffffffu, v, off));
        m = v;   // every thread reduced all 8 partials
    }
    __syncthreads();   // redbuf reused below

    // ---- exp + block-reduce sum ----
    float lsum = 0.0f;
#pragma unroll
    for (int q = 0; q < 8; q++) {
        const float e = __expf(lv[q] - m);
        lv[q] = e;
        lsum += e;
    }
#pragma unroll
    for (int off = 16; off > 0; off >>= 1)
        lsum += __shfl_xor_sync(0xffffffffu, lsum, off);
    if ((tid & 31) == 0) redbuf[tid >> 5] = lsum;
    __syncthreads();
    float stot;
    {
        float v = redbuf[tid & 7];
#pragma unroll
        for (int off = 4; off > 0; off >>= 1)
            v += __shfl_xor_sync(0xffffffffu, v, off);
        stot = v;
    }
    const float rinv = 1.0f / stot;

    float2* prow = reinterpret_cast<float2*>(g_p + (size_t)i * N);
#pragma unroll
    for (int p = 0; p < 4; p++) {
        float2 o;
        o.x = lv[2 * p]     * rinv;
        o.y = lv[2 * p + 1] * rinv;
        prow[p * 256 + tid] = o;
    }
}

// ---------------------------------------------------------------------------
// Kernel D: feature = P @ v  (2048x2048 x 2048x256).
// 64x64 block tile, 4x4 thread tile with f32x2 over column pairs.
// P is stored value-duplicated in smem (u64) so the a-operand is one LDS.64;
// micro-kernel per k-step: 4+2 LDS.64 + 8 FFMA2 = 14 instr for 16 FMA.
// ---------------------------------------------------------------------------
#define D_BK 32
__global__ void __launch_bounds__(256) av_kernel(float* __restrict__ out)
{
    __shared__ u64 psd[D_BK * 65];                       // psd[kk][i], duplicated
    __shared__ __align__(16) float vs[D_BK * 66];        // vs[kk][j]

    const int tid = threadIdx.x;
    const int j0 = blockIdx.x * 64;
    const int i0 = blockIdx.y * 64;
    const int ty = tid >> 4, tx = tid & 15;

    u64 acc2[4][2];
#pragma unroll
    for (int r = 0; r < 4; r++) { acc2[r][0] = 0ULL; acc2[r][1] = 0ULL; }

    for (int kt = 0; kt < N; kt += D_BK) {
        for (int idx = tid; idx < 64 * D_BK; idx += 256) {
            const int kk = idx & (D_BK - 1);
            const int ii = idx >> 5;
            const float v = g_p[(size_t)(i0 + ii) * N + kt + kk];
            psd[kk * 65 + ii] = dup2(v);
        }
        for (int idx = tid; idx < D_BK * 64; idx += 256) {
            const int jj = idx & 63;
            const int kk = idx >> 6;
            vs[kk * 66 + jj] = g_v[(size_t)(kt + kk) * DH + j0 + jj];
        }
        __syncthreads();

#pragma unroll
        for (int kk = 0; kk < D_BK; kk++) {
            u64 a2[4];
#pragma unroll
            for (int r = 0; r < 4; r++) a2[r] = psd[kk * 65 + ty * 4 + r];
            u64 b2v[2];
#pragma unroll
            for (int c = 0; c < 2; c++)
                b2v[c] = *reinterpret_cast<const u64*>(&vs[kk * 66 + tx * 4 + c * 2]);
#pragma unroll
            for (int r = 0; r < 4; r++)
#pragma unroll
                for (int c = 0; c < 2; c++)
                    acc2[r][c] = fma2(a2[r], b2v[c], acc2[r][c]);
        }
        __syncthreads();
    }

#pragma unroll
    for (int r = 0; r < 4; r++) {
        float x0, x1, x2, x3;
        unpack2(acc2[r][0], x0, x1);
        unpack2(acc2[r][1], x2, x3);
        float4 o = make_float4(x0, x1, x2, x3);
        *reinterpret_cast<float4*>(
            &out[(size_t)(i0 + ty * 4 + r) * DH + j0 + tx * 4]) = o;
    }
}

// ---------------------------------------------------------------------------
// Launch. Inputs (metadata order):
//  0 x, 1 adj, 2 dense, 3 Wq, 4 bq, 5 Wk, 6 bk, 7 Wv, 8 bv,
//  9 W1, 10 b1, 11 W2, 12 b2, 13 W3, 14 b3 (softmax-invariant, unused)
// ---------------------------------------------------------------------------
extern "C" void kernel_launch(void* const* d_in, const int* in_sizes, int n_in,
                              void* d_out, int out_size)
{
    const float* x     = (const float*)d_in[0];
    const float* adj   = (const float*)d_in[1];
    const float* dense = (const float*)d_in[2];
    const float* Wq    = (const float*)d_in[3];
    const float* bq    = (const float*)d_in[4];
    const float* Wk    = (const float*)d_in[5];
    const float* bk    = (const float*)d_in[6];
    const float* Wv    = (const float*)d_in[7];
    const float* bv    = (const float*)d_in[8];
    const float* W1    = (const float*)d_in[9];
    const float* b1    = (const float*)d_in[10];
    const float* W2    = (const float*)d_in[11];
    const float* b2    = (const float*)d_in[12];
    const float* W3    = (const float*)d_in[13];
    float* out = (float*)d_out;

    proj_kernel<<<N / A_ROWS, 256>>>(x, Wq, bq, Wk, bk, Wv, bv);
    scores_kernel<<<dim3(N / 64, N / 64), 256>>>();
    mlp_softmax_kernel<<<N, 256>>>(adj, dense, W1, b1, W2, b2, W3);
    av_kernel<<<dim3(DH / 64, N / 64), 256>>>(out);
}

// round 9
// speedup vs baseline: 1.5101x; 1.5101x over previous
#include <cuda_runtime.h>
#include <cuda_bf16.h>
#include <math.h>

// Problem constants
#define N    2048
#define DH   256
#define DK   64
#define FF   32

typedef unsigned long long u64;

// ---------------------------------------------------------------------------
// f32x2 packed helpers (Blackwell sm_100+ only; ptxas never auto-fuses these)
// ---------------------------------------------------------------------------
__device__ __forceinline__ u64 pack2(float lo, float hi) {
    u64 r;
    asm("mov.b64 %0, {%1, %2};" : "=l"(r) : "f"(lo), "f"(hi));
    return r;
}
__device__ __forceinline__ void unpack2(u64 v, float& lo, float& hi) {
    asm("mov.b64 {%0, %1}, %2;" : "=f"(lo), "=f"(hi) : "l"(v));
}
__device__ __forceinline__ u64 fma2(u64 a, u64 b, u64 c) {
    u64 d;
    asm("fma.rn.f32x2 %0, %1, %2, %3;" : "=l"(d) : "l"(a), "l"(b), "l"(c));
    return d;
}
__device__ __forceinline__ u64 dup2(float v) { return pack2(v, v); }
__device__ __forceinline__ u64 relu2(u64 a) {
    float lo, hi;
    unpack2(a, lo, hi);
    lo = fmaxf(lo, 0.0f);
    hi = fmaxf(hi, 0.0f);
    return pack2(lo, hi);
}

// ---------------------------------------------------------------------------
// Scratch (no cudaMalloc allowed)
// ---------------------------------------------------------------------------
__device__ float g_q[N * DK];             // Q(x_j): (N, 64)
__device__ float g_k[N * DK];             // K(x_i): (N, 64)
__device__ float g_v[N * DH];             // V(x_j): (N, 256)
__device__ float g_scores[(size_t)N * N]; // k @ q^T
__device__ float g_p[(size_t)N * N];      // softmax focus
__device__ float g_part[8 * (size_t)N * DH]; // split-K partials for P@V

// ---------------------------------------------------------------------------
// Kernel A: q/k/v projections. 128 blocks x 16 rows. x tile cached in smem.
// k-loop unrolled so LDGs pipeline (MLP>1) instead of serializing at L2 lat.
// ---------------------------------------------------------------------------
#define A_ROWS 16
__global__ void __launch_bounds__(256) proj_kernel(
    const float* __restrict__ x,
    const float* __restrict__ Wq, const float* __restrict__ bq,
    const float* __restrict__ Wk, const float* __restrict__ bk,
    const float* __restrict__ Wv, const float* __restrict__ bv)
{
    __shared__ float xs[A_ROWS * DH];   // 16 KB
    const int tid = threadIdx.x;
    const int r0  = blockIdx.x * A_ROWS;

    for (int idx = tid; idx < A_ROWS * DH; idx += 256)
        xs[idx] = x[(size_t)r0 * DH + idx];
    __syncthreads();

    // 384 output columns total: [0,64) -> q, [64,128) -> k, [128,384) -> v
    for (int g = tid; g < 384; g += 256) {
        const float* W; const float* b; float* out;
        int ld, col;
        if (g < 64)        { W = Wq; b = bq; out = g_q; ld = DK; col = g; }
        else if (g < 128)  { W = Wk; b = bk; out = g_k; ld = DK; col = g - 64; }
        else               { W = Wv; b = bv; out = g_v; ld = DH; col = g - 128; }

        float acc[A_ROWS];
        const float bb = b[col];
#pragma unroll
        for (int r = 0; r < A_ROWS; r++) acc[r] = bb;

#pragma unroll 8
        for (int k = 0; k < DH; k++) {
            const float w = __ldg(&W[k * ld + col]);
#pragma unroll
            for (int r = 0; r < A_ROWS; r++)
                acc[r] = fmaf(xs[r * DH + k], w, acc[r]);
        }
#pragma unroll
        for (int r = 0; r < A_ROWS; r++)
            out[(size_t)(r0 + r) * ld + col] = acc[r];
    }
}

// ---------------------------------------------------------------------------
// Kernel B: scores[i][j] = dot(k_i, q_j). 64x64 tile, 4x4 thread micro-tile,
// f32x2: per c-step 2x LDS.128 + 4 reg-dups + 8 FFMA2 (1 B/FMA, balanced).
// Row pitch 68 floats (272B) keeps 16B alignment for vector LDS.
// ---------------------------------------------------------------------------
__global__ void __launch_bounds__(256) scores_kernel()
{
    __shared__ float ks[64 * 68];  // ks[c][i]
    __shared__ float qs[64 * 68];  // qs[c][j]
    const int tid = threadIdx.x;
    const int j0 = blockIdx.x * 64;
    const int i0 = blockIdx.y * 64;

    for (int idx = tid; idx < 64 * 64; idx += 256) {
        const int row = idx >> 6;   // tile row
        const int c   = idx & 63;   // k-dim
        ks[c * 68 + row] = g_k[(size_t)(i0 + row) * DK + c];
        qs[c * 68 + row] = g_q[(size_t)(j0 + row) * DK + c];
    }
    __syncthreads();

    const int ty = tid >> 4, tx = tid & 15;
    u64 acc[4][2];
#pragma unroll
    for (int r = 0; r < 4; r++) { acc[r][0] = 0ULL; acc[r][1] = 0ULL; }

#pragma unroll 8
    for (int c = 0; c < 64; c++) {
        const float4 a4 = *reinterpret_cast<const float4*>(&ks[c * 68 + ty * 4]);
        const ulonglong2 bq2 = *reinterpret_cast<const ulonglong2*>(&qs[c * 68 + tx * 4]);
        u64 ad[4] = { dup2(a4.x), dup2(a4.y), dup2(a4.z), dup2(a4.w) };
        u64 bb[2] = { bq2.x, bq2.y };
#pragma unroll
        for (int r = 0; r < 4; r++)
#pragma unroll
            for (int cc = 0; cc < 2; cc++)
                acc[r][cc] = fma2(ad[r], bb[cc], acc[r][cc]);
    }

#pragma unroll
    for (int r = 0; r < 4; r++) {
        float x0, x1, x2, x3;
        unpack2(acc[r][0], x0, x1);
        unpack2(acc[r][1], x2, x3);
        float4 o = make_float4(x0, x1, x2, x3);
        *reinterpret_cast<float4*>(
            &g_scores[(size_t)(i0 + ty * 4 + r) * N + j0 + tx * 4]) = o;
    }
}

// ---------------------------------------------------------------------------
// Kernel C: fused per-pair MLP + row softmax -> P.
// One block per row i. 2 super-chunks x 2 j-pairs per thread: each broadcast
// LDS.64 of a W2 element now feeds TWO fma.rn.f32x2 (24% fewer instructions,
// 4 independent accumulator chains). b3 is softmax-invariant and dropped.
// ---------------------------------------------------------------------------
__global__ void __launch_bounds__(256, 1) mlp_softmax_kernel(
    const float* __restrict__ adj,  const float* __restrict__ dense,
    const float* __restrict__ W1,   const float* __restrict__ b1,
    const float* __restrict__ W2,   const float* __restrict__ b2,
    const float* __restrict__ W3)
{
    __shared__ u64 w2p[FF * FF];                       // 8 KB, duplicated pairs
    __shared__ u64 c0p[FF], c1p[FF], c2p[FF], b1p[FF], b2p[FF], w3p[FF];
    __shared__ float redbuf[8];

    const int tid = threadIdx.x;

    if (tid < FF) {
        c0p[tid] = dup2(W1[0 * FF + tid]);   // scores coeff
        c1p[tid] = dup2(W1[1 * FF + tid]);   // adj coeff
        c2p[tid] = dup2(W1[2 * FF + tid]);   // dense coeff
        b1p[tid] = dup2(b1[tid]);
        b2p[tid] = dup2(b2[tid]);
        w3p[tid] = dup2(W3[tid]);
    }
    for (int idx = tid; idx < FF * FF; idx += 256)
        w2p[idx] = dup2(W2[idx]);
    __syncthreads();

    const int i = blockIdx.x;
    const float2* srow = reinterpret_cast<const float2*>(g_scores + (size_t)i * N);
    const float2* arow = reinterpret_cast<const float2*>(adj      + (size_t)i * N);
    const float2* drow = reinterpret_cast<const float2*>(dense    + (size_t)i * N);

    float lv[8];
    float lmax = -1e30f;

#pragma unroll
    for (int p = 0; p < 2; p++) {
        const int jA = p * 512 + tid;        // float2 index, pair A
        const int jB = jA + 256;             // pair B
        const float2 sA = srow[jA], aA = arow[jA], dA = drow[jA];
        const float2 sB = srow[jB], aB = arow[jB], dB = drow[jB];
        const u64 sa = pack2(sA.x, sA.y), av = pack2(aA.x, aA.y), dv = pack2(dA.x, dA.y);
        const u64 sb = pack2(sB.x, sB.y), ab = pack2(aB.x, aB.y), db = pack2(dB.x, dB.y);

        // h1 = relu(s*W1[0] + a*W1[1] + d*W1[2] + b1) for both pairs
        u64 h1a[FF], h1b[FF];
#pragma unroll
        for (int ii = 0; ii < FF; ii++) {
            u64 t = fma2(dv, c2p[ii], b1p[ii]);
            t = fma2(av, c1p[ii], t);
            t = fma2(sa, c0p[ii], t);
            h1a[ii] = relu2(t);
            u64 u = fma2(db, c2p[ii], b1p[ii]);
            u = fma2(ab, c1p[ii], u);
            u = fma2(sb, c0p[ii], u);
            h1b[ii] = relu2(u);
        }

        // logit = sum_o relu(b2[o] + sum_ii h1[ii]*W2[ii][o]) * W3[o]
        u64 lga = 0ULL, lgb = 0ULL;
#pragma unroll 2
        for (int o = 0; o < FF; o++) {
            u64 acca = b2p[o];
            u64 accb = acca;
#pragma unroll
            for (int ii = 0; ii < FF; ii++) {
                const u64 w = w2p[ii * FF + o];
                acca = fma2(h1a[ii], w, acca);
                accb = fma2(h1b[ii], w, accb);
            }
            const u64 w3o = w3p[o];
            lga = fma2(relu2(acca), w3o, lga);
            lgb = fma2(relu2(accb), w3o, lgb);
        }
        unpack2(lga, lv[4 * p],     lv[4 * p + 1]);
        unpack2(lgb, lv[4 * p + 2], lv[4 * p + 3]);
        lmax = fmaxf(lmax, fmaxf(fmaxf(lv[4*p], lv[4*p+1]), fmaxf(lv[4*p+2], lv[4*p+3])));
    }

    // ---- block-reduce max ----
#pragma unroll
    for (int off = 16; off > 0; off >>= 1)
        lmax = fmaxf(lmax, __shfl_xor_sync(0xffffffffu, lmax, off));
    if ((tid & 31) == 0) redbuf[tid >> 5] = lmax;
    __syncthreads();
    float m;
    {
        float v = redbuf[tid & 7];
#pragma unroll
        for (int off = 4; off > 0; off >>= 1)
            v = fmaxf(v, __shfl_xor_sync(0xffffffffu, v, off));
        m = v;   // every thread reduced all 8 partials
    }
    __syncthreads();   // redbuf reused below

    // ---- exp + block-reduce sum ----
    float lsum = 0.0f;
#pragma unroll
    for (int q = 0; q < 8; q++) {
        const float e = __expf(lv[q] - m);
        lv[q] = e;
        lsum += e;
    }
#pragma unroll
    for (int off = 16; off > 0; off >>= 1)
        lsum += __shfl_xor_sync(0xffffffffu, lsum, off);
    if ((tid & 31) == 0) redbuf[tid >> 5] = lsum;
    __syncthreads();
    float stot;
    {
        float v = redbuf[tid & 7];
#pragma unroll
        for (int off = 4; off > 0; off >>= 1)
            v += __shfl_xor_sync(0xffffffffu, v, off);
        stot = v;
    }
    const float rinv = 1.0f / stot;

    float2* prow = reinterpret_cast<float2*>(g_p + (size_t)i * N);
#pragma unroll
    for (int p = 0; p < 2; p++) {
        float2 oA, oB;
        oA.x = lv[4 * p]     * rinv;  oA.y = lv[4 * p + 1] * rinv;
        oB.x = lv[4 * p + 2] * rinv;  oB.y = lv[4 * p + 3] * rinv;
        prow[p * 512 + tid]       = oA;
        prow[p * 512 + 256 + tid] = oB;
    }
}

// ---------------------------------------------------------------------------
// Kernel D: feature = P @ v via split-K (8 ways) into partials + reduce.
// 128x128 block tile, 8x8 thread tile. No smem duplication: a loads as two
// broadcast LDS.128 + register dup (1 B/FMA -> smem crossbar and FMA pipe
// balanced 1:1). grid = 2*16*8 = 256 blocks, 2 CTAs/SM.
// ---------------------------------------------------------------------------
#define AV_BK 16
__global__ void __launch_bounds__(256, 2) av_split_kernel()
{
    __shared__ float ps[AV_BK][132];   // ps[kk][ii] (transposed P), 16B-aligned rows
    __shared__ float vs[AV_BK][132];   // vs[kk][jj]

    const int tid = threadIdx.x;
    const int j0    = blockIdx.x * 128;   // 2 tiles
    const int i0    = blockIdx.y * 128;   // 16 tiles
    const int kbase = blockIdx.z * 256;   // 8 splits
    const int ty = tid >> 4, tx = tid & 15;

    u64 acc[8][4];
#pragma unroll
    for (int r = 0; r < 8; r++)
#pragma unroll
        for (int c = 0; c < 4; c++) acc[r][c] = 0ULL;

    for (int kt = 0; kt < 256; kt += AV_BK) {
        // load P tile: 128 rows x 16 kk -> transposed smem
#pragma unroll
        for (int l = 0; l < 8; l++) {
            const int idx = l * 256 + tid;
            const int ii = idx >> 4;        // 0..127
            const int kk = idx & 15;
            ps[kk][ii] = g_p[(size_t)(i0 + ii) * N + kbase + kt + kk];
        }
        // load V tile: 16 kk x 128 jj
#pragma unroll
        for (int l = 0; l < 8; l++) {
            const int idx = l * 256 + tid;
            const int kk = idx >> 7;        // 0..15
            const int jj = idx & 127;
            vs[kk][jj] = g_v[(size_t)(kbase + kt + kk) * DH + j0 + jj];
        }
        __syncthreads();

#pragma unroll
        for (int kk = 0; kk < AV_BK; kk++) {
            const float4 a0 = *reinterpret_cast<const float4*>(&ps[kk][ty * 8]);
            const float4 a1 = *reinterpret_cast<const float4*>(&ps[kk][ty * 8 + 4]);
            const ulonglong2 b0 = *reinterpret_cast<const ulonglong2*>(&vs[kk][tx * 8]);
            const ulonglong2 b1 = *reinterpret_cast<const ulonglong2*>(&vs[kk][tx * 8 + 4]);
            u64 ad[8] = { dup2(a0.x), dup2(a0.y), dup2(a0.z), dup2(a0.w),
                          dup2(a1.x), dup2(a1.y), dup2(a1.z), dup2(a1.w) };
            u64 bb[4] = { b0.x, b0.y, b1.x, b1.y };
#pragma unroll
            for (int r = 0; r < 8; r++)
#pragma unroll
                for (int c = 0; c < 4; c++)
                    acc[r][c] = fma2(ad[r], bb[c], acc[r][c]);
        }
        __syncthreads();
    }

    float* dst = g_part + (size_t)blockIdx.z * ((size_t)N * DH);
#pragma unroll
    for (int r = 0; r < 8; r++) {
        const int row = i0 + ty * 8 + r;
        float x0, x1, x2, x3, x4, x5, x6, x7;
        unpack2(acc[r][0], x0, x1);
        unpack2(acc[r][1], x2, x3);
        unpack2(acc[r][2], x4, x5);
        unpack2(acc[r][3], x6, x7);
        float4* d4 = reinterpret_cast<float4*>(&dst[(size_t)row * DH + j0 + tx * 8]);
        d4[0] = make_float4(x0, x1, x2, x3);
        d4[1] = make_float4(x4, x5, x6, x7);
    }
}

// Deterministic fixed-order reduction of the 8 split-K partials.
__global__ void __launch_bounds__(256) av_reduce_kernel(float* __restrict__ out)
{
    const int idx = blockIdx.x * 256 + threadIdx.x;   // float4 index, 131072 total
    const float4* p = reinterpret_cast<const float4*>(g_part);
    float4 s = p[idx];
#pragma unroll
    for (int k = 1; k < 8; k++) {
        const float4 v = p[(size_t)k * (N * DH / 4) + idx];
        s.x += v.x; s.y += v.y; s.z += v.z; s.w += v.w;
    }
    reinterpret_cast<float4*>(out)[idx] = s;
}

// ---------------------------------------------------------------------------
// Launch. Inputs (metadata order):
//  0 x, 1 adj, 2 dense, 3 Wq, 4 bq, 5 Wk, 6 bk, 7 Wv, 8 bv,
//  9 W1, 10 b1, 11 W2, 12 b2, 13 W3, 14 b3 (softmax-invariant, unused)
// ---------------------------------------------------------------------------
extern "C" void kernel_launch(void* const* d_in, const int* in_sizes, int n_in,
                              void* d_out, int out_size)
{
    const float* x     = (const float*)d_in[0];
    const float* adj   = (const float*)d_in[1];
    const float* dense = (const float*)d_in[2];
    const float* Wq    = (const float*)d_in[3];
    const float* bq    = (const float*)d_in[4];
    const float* Wk    = (const float*)d_in[5];
    const float* bk    = (const float*)d_in[6];
    const float* Wv    = (const float*)d_in[7];
    const float* bv    = (const float*)d_in[8];
    const float* W1    = (const float*)d_in[9];
    const float* b1    = (const float*)d_in[10];
    const float* W2    = (const float*)d_in[11];
    const float* b2    = (const float*)d_in[12];
    const float* W3    = (const float*)d_in[13];
    float* out = (float*)d_out;

    proj_kernel<<<N / A_ROWS, 256>>>(x, Wq, bq, Wk, bk, Wv, bv);
    scores_kernel<<<dim3(N / 64, N / 64), 256>>>();
    mlp_softmax_kernel<<<N, 256>>>(adj, dense, W1, b1, W2, b2, W3);
    av_split_kernel<<<dim3(2, 16, 8), 256>>>();
    av_reduce_kernel<<<N * DH / 4 / 256, 256>>>(out);
}

// round 13
// speedup vs baseline: 1.6056x; 1.0632x over previous
#include <cuda_runtime.h>
#include <cuda_bf16.h>
#include <math.h>

// Problem constants
#define N    2048
#define DH   256
#define DK   64
#define FF   32

typedef unsigned long long u64;

// ---------------------------------------------------------------------------
// f32x2 packed helpers (portable PTX, sm_100+; ptxas never auto-fuses these)
// ---------------------------------------------------------------------------
__device__ __forceinline__ u64 pack2(float lo, float hi) {
    u64 r;
    asm("mov.b64 %0, {%1, %2};" : "=l"(r) : "f"(lo), "f"(hi));
    return r;
}
__device__ __forceinline__ void unpack2(u64 v, float& lo, float& hi) {
    asm("mov.b64 {%0, %1}, %2;" : "=f"(lo), "=f"(hi) : "l"(v));
}
__device__ __forceinline__ u64 fma2(u64 a, u64 b, u64 c) {
    u64 d;
    asm("fma.rn.f32x2 %0, %1, %2, %3;" : "=l"(d) : "l"(a), "l"(b), "l"(c));
    return d;
}
__device__ __forceinline__ u64 dup2(float v) { return pack2(v, v); }
__device__ __forceinline__ u64 relu2(u64 a) {
    float lo, hi;
    unpack2(a, lo, hi);
    lo = fmaxf(lo, 0.0f);
    hi = fmaxf(hi, 0.0f);
    return pack2(lo, hi);
}

// ---------------------------------------------------------------------------
// Scratch (no cudaMalloc allowed)
// ---------------------------------------------------------------------------
#define KSPLIT 16
__device__ float g_q[N * DK];              // Q(x_j): (N, 64)
__device__ float g_k[N * DK];              // K(x_i): (N, 64)
__device__ float g_v[N * DH];              // V(x_j): (N, 256)
__device__ float g_scores[(size_t)N * N];  // k @ q^T
__device__ float g_p[(size_t)N * N];       // logits, then softmax P (in-place)
__device__ float g_part[KSPLIT * (size_t)N * DH];  // split-K partials for P@V

// ---------------------------------------------------------------------------
// Kernel A: q/k/v projections (unchanged from best)
// ---------------------------------------------------------------------------
#define A_ROWS 16
__global__ void __launch_bounds__(256) proj_kernel(
    const float* __restrict__ x,
    const float* __restrict__ Wq, const float* __restrict__ bq,
    const float* __restrict__ Wk, const float* __restrict__ bk,
    const float* __restrict__ Wv, const float* __restrict__ bv)
{
    __shared__ float xs[A_ROWS * DH];
    const int tid = threadIdx.x;
    const int r0  = blockIdx.x * A_ROWS;

    for (int idx = tid; idx < A_ROWS * DH; idx += 256)
        xs[idx] = x[(size_t)r0 * DH + idx];
    __syncthreads();

    for (int g = tid; g < 384; g += 256) {
        const float* W; const float* b; float* out;
        int ld, col;
        if (g < 64)        { W = Wq; b = bq; out = g_q; ld = DK; col = g; }
        else if (g < 128)  { W = Wk; b = bk; out = g_k; ld = DK; col = g - 64; }
        else               { W = Wv; b = bv; out = g_v; ld = DH; col = g - 128; }

        float acc[A_ROWS];
        const float bb = b[col];
#pragma unroll
        for (int r = 0; r < A_ROWS; r++) acc[r] = bb;

#pragma unroll 8
        for (int k = 0; k < DH; k++) {
            const float w = __ldg(&W[k * ld + col]);
#pragma unroll
            for (int r = 0; r < A_ROWS; r++)
                acc[r] = fmaf(xs[r * DH + k], w, acc[r]);
        }
#pragma unroll
        for (int r = 0; r < A_ROWS; r++)
            out[(size_t)(r0 + r) * ld + col] = acc[r];
    }
}

// ---------------------------------------------------------------------------
// Kernel B: scores = k @ q^T (unchanged from best)
// ---------------------------------------------------------------------------
__global__ void __launch_bounds__(256) scores_kernel()
{
    __shared__ float ks[64 * 68];
    __shared__ float qs[64 * 68];
    const int tid = threadIdx.x;
    const int j0 = blockIdx.x * 64;
    const int i0 = blockIdx.y * 64;

    for (int idx = tid; idx < 64 * 64; idx += 256) {
        const int row = idx >> 6;
        const int c   = idx & 63;
        ks[c * 68 + row] = g_k[(size_t)(i0 + row) * DK + c];
        qs[c * 68 + row] = g_q[(size_t)(j0 + row) * DK + c];
    }
    __syncthreads();

    const int ty = tid >> 4, tx = tid & 15;
    u64 acc[4][2];
#pragma unroll
    for (int r = 0; r < 4; r++) { acc[r][0] = 0ULL; acc[r][1] = 0ULL; }

#pragma unroll 8
    for (int c = 0; c < 64; c++) {
        const float4 a4 = *reinterpret_cast<const float4*>(&ks[c * 68 + ty * 4]);
        const ulonglong2 bq2 = *reinterpret_cast<const ulonglong2*>(&qs[c * 68 + tx * 4]);
        u64 ad[4] = { dup2(a4.x), dup2(a4.y), dup2(a4.z), dup2(a4.w) };
        u64 bb[2] = { bq2.x, bq2.y };
#pragma unroll
        for (int r = 0; r < 4; r++)
#pragma unroll
            for (int cc = 0; cc < 2; cc++)
                acc[r][cc] = fma2(ad[r], bb[cc], acc[r][cc]);
    }

#pragma unroll
    for (int r = 0; r < 4; r++) {
        float x0, x1, x2, x3;
        unpack2(acc[r][0], x0, x1);
        unpack2(acc[r][1], x2, x3);
        float4 o = make_float4(x0, x1, x2, x3);
        *reinterpret_cast<float4*>(
            &g_scores[(size_t)(i0 + ty * 4 + r) * N + j0 + tx * 4]) = o;
    }
}

// ---------------------------------------------------------------------------
// Kernel C1: per-pair MLP -> raw logits (no softmax; pure streaming compute).
// Block = quarter row (512 j = 256 pairs), grid (4, 2048) = 8192 blocks,
// 2 CTAs/SM. 1 j-pair/thread: h1 = 64 regs. Layer-2 loads W2 *vectorized over
// o* (duplicated u64 pairs, LDS.128 covers 2 o's) -> 2 LDS.128 + 4 FFMA2 per
// ii-step, 8 independent acc chains (oq unroll 2). b3 is softmax-invariant.
// ---------------------------------------------------------------------------
__global__ void __launch_bounds__(256, 2) mlp_logits_kernel(
    const float* __restrict__ adj,  const float* __restrict__ dense,
    const float* __restrict__ W1,   const float* __restrict__ b1,
    const float* __restrict__ W2,   const float* __restrict__ b2,
    const float* __restrict__ W3)
{
    __shared__ __align__(16) u64 w2p[FF * FF];   // [ii][o], dup pairs, 8 KB
    __shared__ u64 c0p[FF], c1p[FF], c2p[FF], b1p[FF], b2p[FF], w3p[FF];

    const int tid = threadIdx.x;

    if (tid < FF) {
        c0p[tid] = dup2(W1[0 * FF + tid]);
        c1p[tid] = dup2(W1[1 * FF + tid]);
        c2p[tid] = dup2(W1[2 * FF + tid]);
        b1p[tid] = dup2(b1[tid]);
        b2p[tid] = dup2(b2[tid]);
        w3p[tid] = dup2(W3[tid]);
    }
    for (int idx = tid; idx < FF * FF; idx += 256)
        w2p[idx] = dup2(W2[idx]);          // idx = ii*32 + o (row-major, o fast)
    __syncthreads();

    const int i  = blockIdx.y;
    const int jp = blockIdx.x * 256 + tid;   // pair index within row (0..1023)

    const float2 s = reinterpret_cast<const float2*>(g_scores + (size_t)i * N)[jp];
    const float2 a = reinterpret_cast<const float2*>(adj      + (size_t)i * N)[jp];
    const float2 d = reinterpret_cast<const float2*>(dense    + (size_t)i * N)[jp];
    const u64 s2 = pack2(s.x, s.y);
    const u64 a2 = pack2(a.x, a.y);
    const u64 d2 = pack2(d.x, d.y);

    // layer 1: h1 = relu(s*W1[0] + a*W1[1] + d*W1[2] + b1)
    u64 h1[FF];
#pragma unroll
    for (int ii = 0; ii < FF; ii++) {
        u64 t = fma2(d2, c2p[ii], b1p[ii]);
        t = fma2(a2, c1p[ii], t);
        t = fma2(s2, c0p[ii], t);
        h1[ii] = relu2(t);
    }

    // layer 2 + 3: logit = sum_o relu(b2[o] + sum_ii h1[ii]*W2[ii][o]) * W3[o]
    u64 lg = 0ULL;
#pragma unroll 2
    for (int oq = 0; oq < 8; oq++) {
        const int ob = oq * 4;
        u64 acc0 = b2p[ob + 0], acc1 = b2p[ob + 1];
        u64 acc2 = b2p[ob + 2], acc3 = b2p[ob + 3];
#pragma unroll
        for (int ii = 0; ii < FF; ii++) {
            const ulonglong2 wA =
                *reinterpret_cast<const ulonglong2*>(&w2p[ii * FF + ob]);
            const ulonglong2 wB =
                *reinterpret_cast<const ulonglong2*>(&w2p[ii * FF + ob + 2]);
            acc0 = fma2(h1[ii], wA.x, acc0);
            acc1 = fma2(h1[ii], wA.y, acc1);
            acc2 = fma2(h1[ii], wB.x, acc2);
            acc3 = fma2(h1[ii], wB.y, acc3);
        }
        lg = fma2(relu2(acc0), w3p[ob + 0], lg);
        lg = fma2(relu2(acc1), w3p[ob + 1], lg);
        lg = fma2(relu2(acc2), w3p[ob + 2], lg);
        lg = fma2(relu2(acc3), w3p[ob + 3], lg);
    }

    float lo, hi;
    unpack2(lg, lo, hi);
    reinterpret_cast<float2*>(g_p + (size_t)i * N)[jp] = make_float2(lo, hi);
}

// ---------------------------------------------------------------------------
// Kernel C2: in-place row softmax over g_p (logits -> P). One block per row,
// 256 threads x 8 elements (2x float4), two block reductions.
// ---------------------------------------------------------------------------
__global__ void __launch_bounds__(256) softmax_kernel()
{
    __shared__ float redbuf[8];
    const int tid = threadIdx.x;
    const int i   = blockIdx.x;
    float4* row = reinterpret_cast<float4*>(g_p + (size_t)i * N);

    float4 x0 = row[tid];
    float4 x1 = row[tid + 256];

    float lmax = fmaxf(fmaxf(fmaxf(x0.x, x0.y), fmaxf(x0.z, x0.w)),
                       fmaxf(fmaxf(x1.x, x1.y), fmaxf(x1.z, x1.w)));
#pragma unroll
    for (int off = 16; off > 0; off >>= 1)
        lmax = fmaxf(lmax, __shfl_xor_sync(0xffffffffu, lmax, off));
    if ((tid & 31) == 0) redbuf[tid >> 5] = lmax;
    __syncthreads();
    float m;
    {
        float v = redbuf[tid & 7];
#pragma unroll
        for (int off = 4; off > 0; off >>= 1)
            v = fmaxf(v, __shfl_xor_sync(0xffffffffu, v, off));
        m = v;
    }
    __syncthreads();

    x0.x = __expf(x0.x - m); x0.y = __expf(x0.y - m);
    x0.z = __expf(x0.z - m); x0.w = __expf(x0.w - m);
    x1.x = __expf(x1.x - m); x1.y = __expf(x1.y - m);
    x1.z = __expf(x1.z - m); x1.w = __expf(x1.w - m);

    float lsum = (x0.x + x0.y) + (x0.z + x0.w) + (x1.x + x1.y) + (x1.z + x1.w);
#pragma unroll
    for (int off = 16; off > 0; off >>= 1)
        lsum += __shfl_xor_sync(0xffffffffu, lsum, off);
    if ((tid & 31) == 0) redbuf[tid >> 5] = lsum;
    __syncthreads();
    float stot;
    {
        float v = redbuf[tid & 7];
#pragma unroll
        for (int off = 4; off > 0; off >>= 1)
            v += __shfl_xor_sync(0xffffffffu, v, off);
        stot = v;
    }
    const float rinv = 1.0f / stot;

    x0.x *= rinv; x0.y *= rinv; x0.z *= rinv; x0.w *= rinv;
    x1.x *= rinv; x1.y *= rinv; x1.z *= rinv; x1.w *= rinv;
    row[tid]       = x0;
    row[tid + 256] = x1;
}

// ---------------------------------------------------------------------------
// Kernel D: feature = P @ v via split-K (16 ways -> 512 blocks, 3.5 waves).
// 128x128 block tile, 8x8 thread tile, 1 B/FMA smem traffic.
// ---------------------------------------------------------------------------
#define AV_BK 16
__global__ void __launch_bounds__(256, 2) av_split_kernel()
{
    __shared__ float ps[AV_BK][132];
    __shared__ float vs[AV_BK][132];

    const int tid = threadIdx.x;
    const int j0    = blockIdx.x * 128;           // 2 tiles
    const int i0    = blockIdx.y * 128;           // 16 tiles
    const int kbase = blockIdx.z * (N / KSPLIT);  // 16 splits of 128
    const int ty = tid >> 4, tx = tid & 15;

    u64 acc[8][4];
#pragma unroll
    for (int r = 0; r < 8; r++)
#pragma unroll
        for (int c = 0; c < 4; c++) acc[r][c] = 0ULL;

    for (int kt = 0; kt < N / KSPLIT; kt += AV_BK) {
#pragma unroll
        for (int l = 0; l < 8; l++) {
            const int idx = l * 256 + tid;
            const int ii = idx >> 4;
            const int kk = idx & 15;
            ps[kk][ii] = g_p[(size_t)(i0 + ii) * N + kbase + kt + kk];
        }
#pragma unroll
        for (int l = 0; l < 8; l++) {
            const int idx = l * 256 + tid;
            const int kk = idx >> 7;
            const int jj = idx & 127;
            vs[kk][jj] = g_v[(size_t)(kbase + kt + kk) * DH + j0 + jj];
        }
        __syncthreads();

#pragma unroll
        for (int kk = 0; kk < AV_BK; kk++) {
            const float4 a0 = *reinterpret_cast<const float4*>(&ps[kk][ty * 8]);
            const float4 a1 = *reinterpret_cast<const float4*>(&ps[kk][ty * 8 + 4]);
            const ulonglong2 b0 = *reinterpret_cast<const ulonglong2*>(&vs[kk][tx * 8]);
            const ulonglong2 b1 = *reinterpret_cast<const ulonglong2*>(&vs[kk][tx * 8 + 4]);
            u64 ad[8] = { dup2(a0.x), dup2(a0.y), dup2(a0.z), dup2(a0.w),
                          dup2(a1.x), dup2(a1.y), dup2(a1.z), dup2(a1.w) };
            u64 bb[4] = { b0.x, b0.y, b1.x, b1.y };
#pragma unroll
            for (int r = 0; r < 8; r++)
#pragma unroll
                for (int c = 0; c < 4; c++)
                    acc[r][c] = fma2(ad[r], bb[c], acc[r][c]);
        }
        __syncthreads();
    }

    float* dst = g_part + (size_t)blockIdx.z * ((size_t)N * DH);
#pragma unroll
    for (int r = 0; r < 8; r++) {
        const int row = i0 + ty * 8 + r;
        float x0, x1, x2, x3, x4, x5, x6, x7;
        unpack2(acc[r][0], x0, x1);
        unpack2(acc[r][1], x2, x3);
        unpack2(acc[r][2], x4, x5);
        unpack2(acc[r][3], x6, x7);
        float4* d4 = reinterpret_cast<float4*>(&dst[(size_t)row * DH + j0 + tx * 8]);
        d4[0] = make_float4(x0, x1, x2, x3);
        d4[1] = make_float4(x4, x5, x6, x7);
    }
}

// Deterministic fixed-order reduction of the 16 split-K partials.
__global__ void __launch_bounds__(256) av_reduce_kernel(float* __restrict__ out)
{
    const int idx = blockIdx.x * 256 + threadIdx.x;   // float4 index, 131072 total
    const float4* p = reinterpret_cast<const float4*>(g_part);
    float4 s = p[idx];
#pragma unroll
    for (int k = 1; k < KSPLIT; k++) {
        const float4 v = p[(size_t)k * (N * DH / 4) + idx];
        s.x += v.x; s.y += v.y; s.z += v.z; s.w += v.w;
    }
    reinterpret_cast<float4*>(out)[idx] = s;
}

// ---------------------------------------------------------------------------
// Launch. Inputs (metadata order):
//  0 x, 1 adj, 2 dense, 3 Wq, 4 bq, 5 Wk, 6 bk, 7 Wv, 8 bv,
//  9 W1, 10 b1, 11 W2, 12 b2, 13 W3, 14 b3 (softmax-invariant, unused)
// ---------------------------------------------------------------------------
extern "C" void kernel_launch(void* const* d_in, const int* in_sizes, int n_in,
                              void* d_out, int out_size)
{
    const float* x     = (const float*)d_in[0];
    const float* adj   = (const float*)d_in[1];
    const float* dense = (const float*)d_in[2];
    const float* Wq    = (const float*)d_in[3];
    const float* bq    = (const float*)d_in[4];
    const float* Wk    = (const float*)d_in[5];
    const float* bk    = (const float*)d_in[6];
    const float* Wv    = (const float*)d_in[7];
    const float* bv    = (const float*)d_in[8];
    const float* W1    = (const float*)d_in[9];
    const float* b1    = (const float*)d_in[10];
    const float* W2    = (const float*)d_in[11];
    const float* b2    = (const float*)d_in[12];
    const float* W3    = (const float*)d_in[13];
    float* out = (float*)d_out;

    proj_kernel<<<N / A_ROWS, 256>>>(x, Wq, bq, Wk, bk, Wv, bv);
    scores_kernel<<<dim3(N / 64, N / 64), 256>>>();
    mlp_logits_kernel<<<dim3(4, N), 256>>>(adj, dense, W1, b1, W2, b2, W3);
    softmax_kernel<<<N, 256>>>();
    av_split_kernel<<<dim3(2, 16, KSPLIT), 256>>>();
    av_reduce_kernel<<<N * DH / 4 / 256, 256>>>(out);
}